// round 9
// baseline (speedup 1.0000x reference)
#include <cuda_runtime.h>
#include <math_constants.h>

// Problem constants (fixed instance: B=4, L=4096, H=8, D=64, sample_k=n_top=45)
#define Bq  4
#define Lq  4096
#define Hq  8
#define Dq  64
#define Sq  45      // sample_k
#define Uq  45      // n_top
#define BHq 32
#define NKC 8       // key chunks for split-K attn*V
#define KCS 512     // keys per chunk
#define NKB 32      // 128-key blocks per row for partial softmax stats
#define NB  8       // stage-1 key buckets (512 keys each)
#define MAXP 32768  // pair capacity per bucket (mean 23040, sd ~142)

// ---------------- scratch (device globals: alloc-free) ----------------
__device__ float g_M[BHq * Lq];
__device__ int   g_top[BHq * Uq];
__device__ float g_scores[BHq * Uq * Lq];       // 23.6 MB
__device__ float g_pmax[BHq * Uq * NKB];
__device__ float g_psum[BHq * Uq * NKB];
__device__ float g_rowmax[BHq * Uq];
__device__ float g_rowsum[BHq * Uq];
__device__ float g_part[BHq * NKC * Uq * Dq];
__device__ float g_meanp[BHq * 16 * Dq];
__device__ float g_meanv[BHq * Dq];
// stage-1 bucketed structures (idx is shared across all (b,h): build once)
__device__ int   g_cnt[Lq * NB];                // samples of l landing in bucket
__device__ int   g_off[NB * Lq];                // exclusive prefix within bucket
__device__ int   g_pairs[NB * MAXP];            // j&511 per pair, grouped (bucket,l,s-order)
__device__ float g_pm2[(size_t)BHq * Lq * NB];  // per-(bh,l,bucket) max partial  (4 MB)
__device__ float g_ps2[(size_t)BHq * Lq * NB];  // per-(bh,l,bucket) plain-sum partial

// ---------------- Stage 0a: per-(l,bucket) counts (deterministic) ----------------
__global__ void __launch_bounds__(256) kernel_cnt(const int* __restrict__ idx) {
    int l = blockIdx.x * 256 + threadIdx.x;
    if (l >= Lq) return;
    int c[NB];
#pragma unroll
    for (int b = 0; b < NB; b++) c[b] = 0;
    for (int s = 0; s < Sq; s++) c[idx[l * Sq + s] >> 9]++;
#pragma unroll
    for (int b = 0; b < NB; b++) g_cnt[l * NB + b] = c[b];
}

// ---------------- Stage 0b: per-bucket exclusive scan over l ----------------
__global__ void __launch_bounds__(256) kernel_scan() {
    int bucket = blockIdx.x;
    int t = threadIdx.x;
    __shared__ int ps[256];
    int loc[16];
    int s = 0;
#pragma unroll
    for (int i = 0; i < 16; i++) { loc[i] = s; s += g_cnt[(t * 16 + i) * NB + bucket]; }
    ps[t] = s;
    __syncthreads();
    for (int o = 1; o < 256; o <<= 1) {
        int v = (t >= o) ? ps[t - o] : 0;
        __syncthreads();
        ps[t] += v;
        __syncthreads();
    }
    int excl = (t == 0) ? 0 : ps[t - 1];
#pragma unroll
    for (int i = 0; i < 16; i++) g_off[bucket * Lq + t * 16 + i] = excl + loc[i];
}

// ---------------- Stage 0c: deterministic scatter (s-order within (bucket,l)) ----------------
__global__ void __launch_bounds__(256) kernel_scatter(const int* __restrict__ idx) {
    int l = blockIdx.x * 256 + threadIdx.x;
    if (l >= Lq) return;
    int c[NB];
#pragma unroll
    for (int b = 0; b < NB; b++) c[b] = 0;
    for (int s = 0; s < Sq; s++) {
        int j = idx[l * Sq + s];
        int b = j >> 9;
        g_pairs[b * MAXP + g_off[b * Lq + l] + c[b]] = j & 511;
        c[b]++;
    }
}

// ---------------- Stage 1: bucketed sampled QK^T -> per-bucket (max,sum) partials ----------
// CTA = (bucket, bh, lhalf). K-tile (512 keys x 64) resident in dynamic smem
// (rows padded to 68 floats: 4 groups/warp read 256B rows conflict-free).
// 8-lane group per l: q in registers (8 floats/lane), dot = 8 FMA + 3-step
// butterfly; all pairs of (l,bucket) processed in s-order (deterministic).
__global__ void __launch_bounds__(512) kernel_m2(const float* __restrict__ Q,
                                                 const float* __restrict__ K) {
    extern __shared__ float ks[];                 // 512 * 68 floats = 139,264 B
    int bucket = blockIdx.x, bh = blockIdx.y, lhalf = blockIdx.z;
    int b = bh >> 3, h = bh & 7;
    int tid = threadIdx.x;

    // coalesced tile load: row r at gmem offset r*(Hq*Dq) = r*128 float4
    const float4* K4 = (const float4*)(K + (((size_t)b * Lq + bucket * 512) * Hq + h) * Dq);
    for (int e = tid; e < 512 * 16; e += 512) {
        int r = e >> 4, d4 = e & 15;
        ((float4*)ks)[r * 17 + d4] = K4[(size_t)r * 128 + d4];
    }
    __syncthreads();

    int g = tid >> 3;                              // group 0..63
    int lanei = tid & 7;
    int lbase = lhalf * 2048 + g * 32;

    // depth-1 prefetch of (cnt, start)
    int cnt   = g_cnt[lbase * NB + bucket];
    int start = g_off[bucket * Lq + lbase];
    for (int li = 0; li < 32; li++) {
        int curl = lbase + li;
        int ccnt = cnt, cstart = start;
        if (li < 31) {
            cnt   = g_cnt[(curl + 1) * NB + bucket];
            start = g_off[bucket * Lq + curl + 1];
        }
        float lm = -CUDART_INF_F, lsum = 0.f;
        if (ccnt > 0) {
            const float4* q4 = (const float4*)(Q + (((size_t)b * Lq + curl) * Hq + h) * Dq);
            float4 qa = q4[lanei * 2], qb = q4[lanei * 2 + 1];
            for (int p = 0; p < ccnt; p++) {
                int jloc = g_pairs[bucket * MAXP + cstart + p];
                const float4* kr = (const float4*)&ks[jloc * 68];
                float4 ka = kr[lanei * 2], kb2 = kr[lanei * 2 + 1];
                float dot = qa.x * ka.x;
                dot = fmaf(qa.y, ka.y, dot);
                dot = fmaf(qa.z, ka.z, dot);
                dot = fmaf(qa.w, ka.w, dot);
                dot = fmaf(qb.x, kb2.x, dot);
                dot = fmaf(qb.y, kb2.y, dot);
                dot = fmaf(qb.z, kb2.z, dot);
                dot = fmaf(qb.w, kb2.w, dot);
#pragma unroll
                for (int o = 4; o > 0; o >>= 1)
                    dot += __shfl_xor_sync(0xffffffffu, dot, o);
                lm = fmaxf(lm, dot);
                lsum += dot;
            }
        }
        if (lanei == 0) {
            size_t o = ((size_t)bh * Lq + curl) * NB + bucket;
            g_pm2[o] = lm;
            g_ps2[o] = lsum;
        }
    }
}

// ---------------- Stage 1b: combine bucket partials -> M (fixed order) ----------------
__global__ void __launch_bounds__(256) kernel_mcomb() {
    int i = blockIdx.x * 256 + threadIdx.x;        // (bh,l) flat, 131072
    if (i >= BHq * Lq) return;
    size_t base = (size_t)i * NB;
    float m = -CUDART_INF_F, s = 0.f;
#pragma unroll
    for (int b = 0; b < NB; b++) {
        m = fmaxf(m, g_pm2[base + b]);
        s += g_ps2[base + b];
    }
    g_M[i] = m - s * (1.f / Lq);
}

// ---------------- Stage 2: top-45 per (b,h), stable (lowest index on ties) ----------------
__global__ void __launch_bounds__(256) kernel_topk() {
    int bh = blockIdx.x;
    __shared__ float v[Lq];
    __shared__ float bv[256];
    __shared__ int   bi[256];
    int t = threadIdx.x;
    for (int i = t; i < Lq; i += 256) v[i] = g_M[bh * Lq + i];
    __syncthreads();
    for (int u = 0; u < Uq; u++) {
        float best = -CUDART_INF_F;
        int   besti = Lq;
        for (int i = t; i < Lq; i += 256) {
            float x = v[i];
            if (x > best) { best = x; besti = i; }
        }
        bv[t] = best; bi[t] = besti;
        __syncthreads();
        for (int st = 128; st > 0; st >>= 1) {
            if (t < st) {
                if (bv[t + st] > bv[t] || (bv[t + st] == bv[t] && bi[t + st] < bi[t])) {
                    bv[t] = bv[t + st]; bi[t] = bi[t + st];
                }
            }
            __syncthreads();
        }
        if (t == 0) { g_top[bh * Uq + u] = bi[0]; v[bi[0]] = -CUDART_INF_F; }
        __syncthreads();
    }
}

// ---------------- Stage 3a: scores + fused per-block softmax stats ----------------
__global__ void __launch_bounds__(256) kernel_scores(const float* __restrict__ Q,
                                                     const float* __restrict__ K) {
    __shared__ float Qs[Uq * 65];
    __shared__ float Ks[128 * 65];
    int bh = blockIdx.y;
    int kb = blockIdx.x;
    int b = bh >> 3, h = bh & 7;
    int tid = threadIdx.x;

    for (int e = tid; e < Uq * Dq; e += 256) {
        int u = e >> 6, d = e & 63;
        int row = g_top[bh * Uq + u];
        Qs[u * 65 + d] = Q[(((size_t)b * Lq + row) * Hq + h) * Dq + d];
    }
    int k0 = kb * 128;
    for (int e = tid; e < 128 * Dq; e += 256) {
        int k = e >> 6, d = e & 63;
        Ks[k * 65 + d] = K[(((size_t)b * Lq + k0 + k) * Hq + h) * Dq + d];
    }
    __syncthreads();

    int tu = tid >> 4, tk = tid & 15;
    float acc[3][8];
#pragma unroll
    for (int r = 0; r < 3; r++)
#pragma unroll
        for (int j = 0; j < 8; j++) acc[r][j] = 0.f;

#pragma unroll 4
    for (int d = 0; d < Dq; d++) {
        float qv[3];
#pragma unroll
        for (int r = 0; r < 3; r++) {
            int u = tu + 16 * r;
            qv[r] = (u < Uq) ? Qs[u * 65 + d] : 0.f;
        }
        float kv[8];
#pragma unroll
        for (int j = 0; j < 8; j++) kv[j] = Ks[(tk + 16 * j) * 65 + d];
#pragma unroll
        for (int r = 0; r < 3; r++)
#pragma unroll
            for (int j = 0; j < 8; j++) acc[r][j] = fmaf(qv[r], kv[j], acc[r][j]);
    }

#pragma unroll
    for (int r = 0; r < 3; r++) {
        int u = tu + 16 * r;
        float sc[8];
#pragma unroll
        for (int j = 0; j < 8; j++) sc[j] = acc[r][j] * 0.125f;
        if (u < Uq) {
#pragma unroll
            for (int j = 0; j < 8; j++)
                g_scores[(bh * Uq + u) * Lq + k0 + tk + 16 * j] = sc[j];
        }
        float m = sc[0];
#pragma unroll
        for (int j = 1; j < 8; j++) m = fmaxf(m, sc[j]);
#pragma unroll
        for (int o = 8; o > 0; o >>= 1) m = fmaxf(m, __shfl_xor_sync(0xffffffffu, m, o));
        float s = 0.f;
#pragma unroll
        for (int j = 0; j < 8; j++) s += expf(sc[j] - m);
#pragma unroll
        for (int o = 8; o > 0; o >>= 1) s += __shfl_xor_sync(0xffffffffu, s, o);
        if (tk == 0 && u < Uq) {
            g_pmax[(bh * Uq + u) * NKB + kb] = m;
            g_psum[(bh * Uq + u) * NKB + kb] = s;
        }
    }
}

// ---------------- Stage 3b: combine 32 block partials -> row max / row sum ----------------
__global__ void __launch_bounds__(256) kernel_comb() {
    int gw = blockIdx.x * 8 + (threadIdx.x >> 5);
    if (gw >= BHq * Uq) return;
    int lane = threadIdx.x & 31;
    float pm = g_pmax[gw * NKB + lane];
    float ps = g_psum[gw * NKB + lane];
    float rm = pm;
#pragma unroll
    for (int o = 16; o > 0; o >>= 1) rm = fmaxf(rm, __shfl_xor_sync(0xffffffffu, rm, o));
    float c = ps * expf(pm - rm);
#pragma unroll
    for (int o = 16; o > 0; o >>= 1) c += __shfl_xor_sync(0xffffffffu, c, o);
    if (lane == 0) { g_rowmax[gw] = rm; g_rowsum[gw] = c; }
}

// ---------------- Stage 3c: split-K partial upd[u][d] = sum_k w[u,k] * V[k,d] ----------------
__global__ void __launch_bounds__(256) kernel_updpart(const float* __restrict__ V) {
    __shared__ float Vs[64 * 65];
    __shared__ float Ws[Uq * 65];
    int bh = blockIdx.y;
    int kc = blockIdx.x;
    int b = bh >> 3, h = bh & 7;
    int tid = threadIdx.x;
    int tu = tid >> 4, td = tid & 15;

    float acc[3][4];
#pragma unroll
    for (int r = 0; r < 3; r++)
#pragma unroll
        for (int j = 0; j < 4; j++) acc[r][j] = 0.f;

    for (int sub = 0; sub < 8; sub++) {
        int kbase = kc * KCS + sub * 64;
        for (int e = tid; e < 64 * 64; e += 256) {
            int k = e >> 6, d = e & 63;
            Vs[k * 65 + d] = V[(((size_t)b * Lq + kbase + k) * Hq + h) * Dq + d];
        }
        for (int e = tid; e < Uq * 64; e += 256) {
            int u = e >> 6, k = e & 63;
            Ws[u * 65 + k] = expf(g_scores[(bh * Uq + u) * Lq + kbase + k] - g_rowmax[bh * Uq + u]);
        }
        __syncthreads();
#pragma unroll 4
        for (int k = 0; k < 64; k++) {
            float wv[3];
#pragma unroll
            for (int r = 0; r < 3; r++) {
                int u = tu + 16 * r;
                wv[r] = (u < Uq) ? Ws[u * 65 + k] : 0.f;
            }
            float vv[4];
#pragma unroll
            for (int j = 0; j < 4; j++) vv[j] = Vs[k * 65 + td + 16 * j];
#pragma unroll
            for (int r = 0; r < 3; r++)
#pragma unroll
                for (int j = 0; j < 4; j++) acc[r][j] = fmaf(wv[r], vv[j], acc[r][j]);
        }
        __syncthreads();
    }
#pragma unroll
    for (int r = 0; r < 3; r++) {
        int u = tu + 16 * r;
        if (u < Uq) {
#pragma unroll
            for (int j = 0; j < 4; j++)
                g_part[((bh * NKC + kc) * Uq + u) * Dq + td + 16 * j] = acc[r][j];
        }
    }
}

// ---------------- Stage 4: V mean ----------------
__global__ void __launch_bounds__(256) kernel_meanpart(const float* __restrict__ V) {
    int lc = blockIdx.x;
    int bh = blockIdx.y;
    int b = bh >> 3, h = bh & 7;
    int tid = threadIdx.x;
    int d = tid & 63, c = tid >> 6;
    __shared__ float red[256];
    float s = 0.f;
    int lb = lc * 256 + c * 64;
    for (int i = 0; i < 64; i++)
        s += V[(((size_t)b * Lq + lb + i) * Hq + h) * Dq + d];
    red[tid] = s;
    __syncthreads();
    if (c == 0)
        g_meanp[(bh * 16 + lc) * Dq + d] = red[d] + red[64 + d] + red[128 + d] + red[192 + d];
}

__global__ void __launch_bounds__(256) kernel_meancomb() {
    int e = blockIdx.x * 256 + threadIdx.x;
    if (e >= BHq * Dq) return;
    int bh = e >> 6, d = e & 63;
    float s = 0.f;
#pragma unroll
    for (int lc = 0; lc < 16; lc++) s += g_meanp[(bh * 16 + lc) * Dq + d];
    g_meanv[bh * Dq + d] = s * (1.f / Lq);
}

// ---------------- Stage 5: broadcast fill ----------------
__global__ void __launch_bounds__(256) kernel_fill(float4* __restrict__ out) {
    int i = blockIdx.x * 256 + threadIdx.x;
    int bh = i >> 16;
    int d4 = i & 15;
    out[i] = ((const float4*)g_meanv)[bh * 16 + d4];
}

// ---------------- Stage 6: reduce split-K partials, normalize, scatter ----------------
__global__ void __launch_bounds__(256) kernel_final(float* __restrict__ out) {
    int e = blockIdx.x * 256 + threadIdx.x;
    if (e >= BHq * Uq * Dq) return;
    int d = e & 63;
    int t = e >> 6;
    int u = t % Uq;
    int bh = t / Uq;
    float s = 0.f;
#pragma unroll
    for (int c = 0; c < NKC; c++) s += g_part[((bh * NKC + c) * Uq + u) * Dq + d];
    s /= g_rowsum[bh * Uq + u];
    int row = g_top[bh * Uq + u];
    out[((size_t)bh * Lq + row) * Dq + d] = s;
}

// ---------------- launch ----------------
extern "C" void kernel_launch(void* const* d_in, const int* in_sizes, int n_in,
                              void* d_out, int out_size) {
    const float* Q   = (const float*)d_in[0];
    const float* K   = (const float*)d_in[1];
    const float* V   = (const float*)d_in[2];
    const int*   idx = (const int*)d_in[3];
    float* out = (float*)d_out;

    const int M2_SMEM = 512 * 68 * 4;   // 139,264 B dynamic smem
    static bool attr_set = false;
    if (!attr_set) {
        cudaFuncSetAttribute(kernel_m2, cudaFuncAttributeMaxDynamicSharedMemorySize, M2_SMEM);
        attr_set = true;
    }

    kernel_cnt     <<<Lq / 256, 256>>>(idx);
    kernel_scan    <<<NB, 256>>>();
    kernel_scatter <<<Lq / 256, 256>>>(idx);
    kernel_m2      <<<dim3(NB, BHq, 2), 512, M2_SMEM>>>(Q, K);
    kernel_mcomb   <<<(BHq * Lq) / 256, 256>>>();
    kernel_topk    <<<BHq, 256>>>();
    kernel_scores  <<<dim3(Lq / 128, BHq), 256>>>(Q, K);
    kernel_comb    <<<(BHq * Uq + 7) / 8, 256>>>();
    kernel_updpart <<<dim3(NKC, BHq), 256>>>(V);
    kernel_meanpart<<<dim3(16, BHq), 256>>>(V);
    kernel_meancomb<<<(BHq * Dq + 255) / 256, 256>>>();
    kernel_fill    <<<(BHq * Lq * Dq / 4) / 256, 256>>>((float4*)out);
    kernel_final   <<<(BHq * Uq * Dq + 255) / 256, 256>>>(out);
}

// round 10
// speedup vs baseline: 2.3605x; 2.3605x over previous
#include <cuda_runtime.h>
#include <math_constants.h>

// Problem constants (fixed instance: B=4, L=4096, H=8, D=64, sample_k=n_top=45)
#define Bq  4
#define Lq  4096
#define Hq  8
#define Dq  64
#define Sq  45      // sample_k
#define Uq  45      // n_top
#define BHq 32
#define NKC 8       // key chunks for split-K attn*V
#define KCS 512     // keys per chunk
#define NKB 32      // 128-key blocks per row for partial softmax stats
#define NB  8       // stage-1 key buckets (512 keys each)
#define MAXP 32768  // pair capacity per bucket (mean 23040, sd ~142)
#define PCAP 5120   // smem pair-slab capacity per 256-l block (mean 1440, sd ~36)

// ---------------- scratch (device globals: alloc-free) ----------------
__device__ float g_M[BHq * Lq];
__device__ int   g_top[BHq * Uq];
__device__ float g_scores[BHq * Uq * Lq];       // 23.6 MB
__device__ float g_pmax[BHq * Uq * NKB];
__device__ float g_psum[BHq * Uq * NKB];
__device__ float g_rowmax[BHq * Uq];
__device__ float g_rowsum[BHq * Uq];
__device__ float g_part[BHq * NKC * Uq * Dq];
__device__ float g_meanp[BHq * 16 * Dq];
__device__ float g_meanv[BHq * Dq];
// stage-1 bucketed structures (idx is shared across all (b,h): build once)
__device__ int   g_cnt[Lq * NB];                // samples of l landing in bucket
__device__ int   g_off[NB * Lq];                // exclusive prefix within bucket
__device__ int   g_btot[NB];                    // total pairs per bucket
__device__ int   g_pairs[NB * MAXP];            // j&511 per pair, grouped (bucket,l,s-order)
__device__ float g_pm2[(size_t)BHq * Lq * NB];  // per-(bh,l,bucket) max partial
__device__ float g_ps2[(size_t)BHq * Lq * NB];  // per-(bh,l,bucket) plain-sum partial

// ---- cp.async helpers ----
__device__ __forceinline__ void cp_async16(void* smem_dst, const void* gsrc) {
    unsigned s = (unsigned)__cvta_generic_to_shared(smem_dst);
    asm volatile("cp.async.ca.shared.global [%0], [%1], 16;\n" :: "r"(s), "l"(gsrc));
}
__device__ __forceinline__ void cp_async_wait_all() {
    asm volatile("cp.async.commit_group;\n");
    asm volatile("cp.async.wait_group 0;\n");
}

// ---------------- Stage 0a: per-(l,bucket) counts (deterministic) ----------------
__global__ void __launch_bounds__(256) kernel_cnt(const int* __restrict__ idx) {
    int l = blockIdx.x * 256 + threadIdx.x;
    if (l >= Lq) return;
    int c[NB];
#pragma unroll
    for (int b = 0; b < NB; b++) c[b] = 0;
    for (int s = 0; s < Sq; s++) c[idx[l * Sq + s] >> 9]++;
#pragma unroll
    for (int b = 0; b < NB; b++) g_cnt[l * NB + b] = c[b];
}

// ---------------- Stage 0b: per-bucket exclusive scan over l ----------------
__global__ void __launch_bounds__(256) kernel_scan() {
    int bucket = blockIdx.x;
    int t = threadIdx.x;
    __shared__ int ps[256];
    int loc[16];
    int s = 0;
#pragma unroll
    for (int i = 0; i < 16; i++) { loc[i] = s; s += g_cnt[(t * 16 + i) * NB + bucket]; }
    ps[t] = s;
    __syncthreads();
    for (int o = 1; o < 256; o <<= 1) {
        int v = (t >= o) ? ps[t - o] : 0;
        __syncthreads();
        ps[t] += v;
        __syncthreads();
    }
    int excl = (t == 0) ? 0 : ps[t - 1];
#pragma unroll
    for (int i = 0; i < 16; i++) g_off[bucket * Lq + t * 16 + i] = excl + loc[i];
    if (t == 255) g_btot[bucket] = ps[255];
}

// ---------------- Stage 0c: deterministic scatter (s-order within (bucket,l)) ----------------
__global__ void __launch_bounds__(256) kernel_scatter(const int* __restrict__ idx) {
    int l = blockIdx.x * 256 + threadIdx.x;
    if (l >= Lq) return;
    int c[NB];
#pragma unroll
    for (int b = 0; b < NB; b++) c[b] = 0;
    for (int s = 0; s < Sq; s++) {
        int j = idx[l * Sq + s];
        int b = j >> 9;
        g_pairs[b * MAXP + g_off[b * Lq + l] + c[b]] = j & 511;
        c[b]++;
    }
}

// ---------------- Stage 1: bucketed sampled QK^T, thread-per-(l,bucket) ----------------
// CTA = (bucket, bh, lhalf of 2048 l's), 256 threads. K-tile (512x68 floats)
// loaded ONCE via cp.async; loop over 8 l-blocks of 256: stage Q-tile (256x68)
// + the block's contiguous pair slab in smem, then each thread computes all
// pairs of its own l: q row in 16 float4 regs (conflict-free LDS), 16 LDS.128
// per pair from the K-tile, 4 independent FMA chains, NO shuffles, no
// cross-lane reduction. Fully deterministic s-order accumulation.
__global__ void __launch_bounds__(256) kernel_m3(const float* __restrict__ Q,
                                                 const float* __restrict__ K) {
    extern __shared__ float smem[];
    float* ks = smem;                    // 512*68 = 34816 floats
    float* qs = smem + 512 * 68;         // 256*68 = 17408 floats
    int*   sp = (int*)(smem + 512 * 68 + 256 * 68);   // PCAP ints

    int bucket = blockIdx.x, bh = blockIdx.y, lhalf = blockIdx.z;
    int b = bh >> 3, h = bh & 7;
    int tid = threadIdx.x;

    // K tile: 512 rows x 16 float4, gmem row stride = Hq*Dq = 512 floats
    const float* Kbase = K + (((size_t)b * Lq + bucket * 512) * Hq + h) * Dq;
    for (int e = tid; e < 512 * 16; e += 256) {
        int r = e >> 4, i = e & 15;
        cp_async16(&ks[r * 68 + i * 4], Kbase + (size_t)r * 512 + i * 4);
    }

    for (int it = 0; it < 8; it++) {
        int l0 = lhalf * 2048 + it * 256;
        if (it > 0) __syncthreads();     // previous compute done before overwrite

        // Q tile for this l-block
        const float* Qbase = Q + (((size_t)b * Lq + l0) * Hq + h) * Dq;
        for (int e = tid; e < 256 * 16; e += 256) {
            int r = e >> 4, i = e & 15;
            cp_async16(&qs[r * 68 + i * 4], Qbase + (size_t)r * 512 + i * 4);
        }
        // contiguous pair slab for l0..l0+255 (pairs sorted by l within bucket)
        int pairlo = g_off[bucket * Lq + l0];
        int pairhi = (l0 + 256 < Lq) ? g_off[bucket * Lq + l0 + 256] : g_btot[bucket];
        int n = pairhi - pairlo;
        int nl = n < PCAP ? n : PCAP;
        for (int e = tid; e < nl; e += 256) sp[e] = g_pairs[bucket * MAXP + pairlo + e];

        cp_async_wait_all();
        __syncthreads();

        int l = l0 + tid;
        int cnt = g_cnt[l * NB + bucket];
        int lst = g_off[bucket * Lq + l] - pairlo;   // local start in slab

        // q row -> registers (phase-conflict-free: banks 4(t+i) mod 32)
        float4 q[16];
        const float4* qrow = (const float4*)&qs[tid * 68];
#pragma unroll
        for (int i = 0; i < 16; i++) q[i] = qrow[i];

        float lm = -CUDART_INF_F, lsum = 0.f;
        for (int p = 0; p < cnt; p++) {
            int pi = lst + p;
            int jloc = (pi < PCAP) ? sp[pi] : g_pairs[bucket * MAXP + pairlo + pi];
            const float4* kr = (const float4*)&ks[jloc * 68];
            float a0 = 0.f, a1 = 0.f, a2 = 0.f, a3 = 0.f;
#pragma unroll
            for (int i = 0; i < 4; i++) {
                float4 k0 = kr[i * 4 + 0], k1 = kr[i * 4 + 1];
                float4 k2 = kr[i * 4 + 2], k3 = kr[i * 4 + 3];
                float4 q0 = q[i * 4 + 0], q1 = q[i * 4 + 1];
                float4 q2 = q[i * 4 + 2], q3 = q[i * 4 + 3];
                a0 = fmaf(q0.x, k0.x, a0); a0 = fmaf(q0.y, k0.y, a0);
                a0 = fmaf(q0.z, k0.z, a0); a0 = fmaf(q0.w, k0.w, a0);
                a1 = fmaf(q1.x, k1.x, a1); a1 = fmaf(q1.y, k1.y, a1);
                a1 = fmaf(q1.z, k1.z, a1); a1 = fmaf(q1.w, k1.w, a1);
                a2 = fmaf(q2.x, k2.x, a2); a2 = fmaf(q2.y, k2.y, a2);
                a2 = fmaf(q2.z, k2.z, a2); a2 = fmaf(q2.w, k2.w, a2);
                a3 = fmaf(q3.x, k3.x, a3); a3 = fmaf(q3.y, k3.y, a3);
                a3 = fmaf(q3.z, k3.z, a3); a3 = fmaf(q3.w, k3.w, a3);
            }
            float dot = (a0 + a1) + (a2 + a3);
            lm = fmaxf(lm, dot);
            lsum += dot;
        }
        size_t o = ((size_t)bh * Lq + l) * NB + bucket;
        g_pm2[o] = lm;
        g_ps2[o] = lsum;
    }
}

// ---------------- Stage 1b: combine bucket partials -> M (fixed order) ----------------
__global__ void __launch_bounds__(256) kernel_mcomb() {
    int i = blockIdx.x * 256 + threadIdx.x;        // (bh,l) flat
    if (i >= BHq * Lq) return;
    size_t base = (size_t)i * NB;
    float m = -CUDART_INF_F, s = 0.f;
#pragma unroll
    for (int b = 0; b < NB; b++) {
        m = fmaxf(m, g_pm2[base + b]);
        s += g_ps2[base + b];
    }
    g_M[i] = m - s * (1.f / Lq);
}

// ---------------- Stage 2: top-45 per (b,h), stable (lowest index on ties) ----------------
__global__ void __launch_bounds__(256) kernel_topk() {
    int bh = blockIdx.x;
    __shared__ float v[Lq];
    __shared__ float bv[256];
    __shared__ int   bi[256];
    int t = threadIdx.x;
    for (int i = t; i < Lq; i += 256) v[i] = g_M[bh * Lq + i];
    __syncthreads();
    for (int u = 0; u < Uq; u++) {
        float best = -CUDART_INF_F;
        int   besti = Lq;
        for (int i = t; i < Lq; i += 256) {
            float x = v[i];
            if (x > best) { best = x; besti = i; }
        }
        bv[t] = best; bi[t] = besti;
        __syncthreads();
        for (int st = 128; st > 0; st >>= 1) {
            if (t < st) {
                if (bv[t + st] > bv[t] || (bv[t + st] == bv[t] && bi[t + st] < bi[t])) {
                    bv[t] = bv[t + st]; bi[t] = bi[t + st];
                }
            }
            __syncthreads();
        }
        if (t == 0) { g_top[bh * Uq + u] = bi[0]; v[bi[0]] = -CUDART_INF_F; }
        __syncthreads();
    }
}

// ---------------- Stage 3a: scores + fused per-block softmax stats ----------------
__global__ void __launch_bounds__(256) kernel_scores(const float* __restrict__ Q,
                                                     const float* __restrict__ K) {
    __shared__ float Qs[Uq * 65];
    __shared__ float Ks[128 * 65];
    int bh = blockIdx.y;
    int kb = blockIdx.x;
    int b = bh >> 3, h = bh & 7;
    int tid = threadIdx.x;

    for (int e = tid; e < Uq * Dq; e += 256) {
        int u = e >> 6, d = e & 63;
        int row = g_top[bh * Uq + u];
        Qs[u * 65 + d] = Q[(((size_t)b * Lq + row) * Hq + h) * Dq + d];
    }
    int k0 = kb * 128;
    for (int e = tid; e < 128 * Dq; e += 256) {
        int k = e >> 6, d = e & 63;
        Ks[k * 65 + d] = K[(((size_t)b * Lq + k0 + k) * Hq + h) * Dq + d];
    }
    __syncthreads();

    int tu = tid >> 4, tk = tid & 15;
    float acc[3][8];
#pragma unroll
    for (int r = 0; r < 3; r++)
#pragma unroll
        for (int j = 0; j < 8; j++) acc[r][j] = 0.f;

#pragma unroll 4
    for (int d = 0; d < Dq; d++) {
        float qv[3];
#pragma unroll
        for (int r = 0; r < 3; r++) {
            int u = tu + 16 * r;
            qv[r] = (u < Uq) ? Qs[u * 65 + d] : 0.f;
        }
        float kv[8];
#pragma unroll
        for (int j = 0; j < 8; j++) kv[j] = Ks[(tk + 16 * j) * 65 + d];
#pragma unroll
        for (int r = 0; r < 3; r++)
#pragma unroll
            for (int j = 0; j < 8; j++) acc[r][j] = fmaf(qv[r], kv[j], acc[r][j]);
    }

#pragma unroll
    for (int r = 0; r < 3; r++) {
        int u = tu + 16 * r;
        float sc[8];
#pragma unroll
        for (int j = 0; j < 8; j++) sc[j] = acc[r][j] * 0.125f;
        if (u < Uq) {
#pragma unroll
            for (int j = 0; j < 8; j++)
                g_scores[(bh * Uq + u) * Lq + k0 + tk + 16 * j] = sc[j];
        }
        float m = sc[0];
#pragma unroll
        for (int j = 1; j < 8; j++) m = fmaxf(m, sc[j]);
#pragma unroll
        for (int o = 8; o > 0; o >>= 1) m = fmaxf(m, __shfl_xor_sync(0xffffffffu, m, o));
        float s = 0.f;
#pragma unroll
        for (int j = 0; j < 8; j++) s += expf(sc[j] - m);
#pragma unroll
        for (int o = 8; o > 0; o >>= 1) s += __shfl_xor_sync(0xffffffffu, s, o);
        if (tk == 0 && u < Uq) {
            g_pmax[(bh * Uq + u) * NKB + kb] = m;
            g_psum[(bh * Uq + u) * NKB + kb] = s;
        }
    }
}

// ---------------- Stage 3b: combine 32 block partials -> row max / row sum ----------------
__global__ void __launch_bounds__(256) kernel_comb() {
    int gw = blockIdx.x * 8 + (threadIdx.x >> 5);
    if (gw >= BHq * Uq) return;
    int lane = threadIdx.x & 31;
    float pm = g_pmax[gw * NKB + lane];
    float ps = g_psum[gw * NKB + lane];
    float rm = pm;
#pragma unroll
    for (int o = 16; o > 0; o >>= 1) rm = fmaxf(rm, __shfl_xor_sync(0xffffffffu, rm, o));
    float c = ps * expf(pm - rm);
#pragma unroll
    for (int o = 16; o > 0; o >>= 1) c += __shfl_xor_sync(0xffffffffu, c, o);
    if (lane == 0) { g_rowmax[gw] = rm; g_rowsum[gw] = c; }
}

// ---------------- Stage 3c: split-K partial upd[u][d] = sum_k w[u,k] * V[k,d] ----------------
__global__ void __launch_bounds__(256) kernel_updpart(const float* __restrict__ V) {
    __shared__ float Vs[64 * 65];
    __shared__ float Ws[Uq * 65];
    int bh = blockIdx.y;
    int kc = blockIdx.x;
    int b = bh >> 3, h = bh & 7;
    int tid = threadIdx.x;
    int tu = tid >> 4, td = tid & 15;

    float acc[3][4];
#pragma unroll
    for (int r = 0; r < 3; r++)
#pragma unroll
        for (int j = 0; j < 4; j++) acc[r][j] = 0.f;

    for (int sub = 0; sub < 8; sub++) {
        int kbase = kc * KCS + sub * 64;
        for (int e = tid; e < 64 * 64; e += 256) {
            int k = e >> 6, d = e & 63;
            Vs[k * 65 + d] = V[(((size_t)b * Lq + kbase + k) * Hq + h) * Dq + d];
        }
        for (int e = tid; e < Uq * 64; e += 256) {
            int u = e >> 6, k = e & 63;
            Ws[u * 65 + k] = expf(g_scores[(bh * Uq + u) * Lq + kbase + k] - g_rowmax[bh * Uq + u]);
        }
        __syncthreads();
#pragma unroll 4
        for (int k = 0; k < 64; k++) {
            float wv[3];
#pragma unroll
            for (int r = 0; r < 3; r++) {
                int u = tu + 16 * r;
                wv[r] = (u < Uq) ? Ws[u * 65 + k] : 0.f;
            }
            float vv[4];
#pragma unroll
            for (int j = 0; j < 4; j++) vv[j] = Vs[k * 65 + td + 16 * j];
#pragma unroll
            for (int r = 0; r < 3; r++)
#pragma unroll
                for (int j = 0; j < 4; j++) acc[r][j] = fmaf(wv[r], vv[j], acc[r][j]);
        }
        __syncthreads();
    }
#pragma unroll
    for (int r = 0; r < 3; r++) {
        int u = tu + 16 * r;
        if (u < Uq) {
#pragma unroll
            for (int j = 0; j < 4; j++)
                g_part[((bh * NKC + kc) * Uq + u) * Dq + td + 16 * j] = acc[r][j];
        }
    }
}

// ---------------- Stage 4: V mean ----------------
__global__ void __launch_bounds__(256) kernel_meanpart(const float* __restrict__ V) {
    int lc = blockIdx.x;
    int bh = blockIdx.y;
    int b = bh >> 3, h = bh & 7;
    int tid = threadIdx.x;
    int d = tid & 63, c = tid >> 6;
    __shared__ float red[256];
    float s = 0.f;
    int lb = lc * 256 + c * 64;
    for (int i = 0; i < 64; i++)
        s += V[(((size_t)b * Lq + lb + i) * Hq + h) * Dq + d];
    red[tid] = s;
    __syncthreads();
    if (c == 0)
        g_meanp[(bh * 16 + lc) * Dq + d] = red[d] + red[64 + d] + red[128 + d] + red[192 + d];
}

__global__ void __launch_bounds__(256) kernel_meancomb() {
    int e = blockIdx.x * 256 + threadIdx.x;
    if (e >= BHq * Dq) return;
    int bh = e >> 6, d = e & 63;
    float s = 0.f;
#pragma unroll
    for (int lc = 0; lc < 16; lc++) s += g_meanp[(bh * 16 + lc) * Dq + d];
    g_meanv[bh * Dq + d] = s * (1.f / Lq);
}

// ---------------- Stage 5: broadcast fill ----------------
__global__ void __launch_bounds__(256) kernel_fill(float4* __restrict__ out) {
    int i = blockIdx.x * 256 + threadIdx.x;
    int bh = i >> 16;
    int d4 = i & 15;
    out[i] = ((const float4*)g_meanv)[bh * 16 + d4];
}

// ---------------- Stage 6: reduce split-K partials, normalize, scatter ----------------
__global__ void __launch_bounds__(256) kernel_final(float* __restrict__ out) {
    int e = blockIdx.x * 256 + threadIdx.x;
    if (e >= BHq * Uq * Dq) return;
    int d = e & 63;
    int t = e >> 6;
    int u = t % Uq;
    int bh = t / Uq;
    float s = 0.f;
#pragma unroll
    for (int c = 0; c < NKC; c++) s += g_part[((bh * NKC + c) * Uq + u) * Dq + d];
    s /= g_rowsum[bh * Uq + u];
    int row = g_top[bh * Uq + u];
    out[((size_t)bh * Lq + row) * Dq + d] = s;
}

// ---------------- launch ----------------
extern "C" void kernel_launch(void* const* d_in, const int* in_sizes, int n_in,
                              void* d_out, int out_size) {
    const float* Q   = (const float*)d_in[0];
    const float* K   = (const float*)d_in[1];
    const float* V   = (const float*)d_in[2];
    const int*   idx = (const int*)d_in[3];
    float* out = (float*)d_out;

    const int M3_SMEM = (512 * 68 + 256 * 68) * 4 + PCAP * 4;   // 229,376 B
    static bool attr_set = false;
    if (!attr_set) {
        cudaFuncSetAttribute(kernel_m3, cudaFuncAttributeMaxDynamicSharedMemorySize, M3_SMEM);
        attr_set = true;
    }

    kernel_cnt     <<<Lq / 256, 256>>>(idx);
    kernel_scan    <<<NB, 256>>>();
    kernel_scatter <<<Lq / 256, 256>>>(idx);
    kernel_m3      <<<dim3(NB, BHq, 2), 256, M3_SMEM>>>(Q, K);
    kernel_mcomb   <<<(BHq * Lq) / 256, 256>>>();
    kernel_topk    <<<BHq, 256>>>();
    kernel_scores  <<<dim3(Lq / 128, BHq), 256>>>(Q, K);
    kernel_comb    <<<(BHq * Uq + 7) / 8, 256>>>();
    kernel_updpart <<<dim3(NKC, BHq), 256>>>(V);
    kernel_meanpart<<<dim3(16, BHq), 256>>>(V);
    kernel_meancomb<<<(BHq * Dq + 255) / 256, 256>>>();
    kernel_fill    <<<(BHq * Lq * Dq / 4) / 256, 256>>>((float4*)out);
    kernel_final   <<<(BHq * Uq * Dq + 255) / 256, 256>>>(out);
}